// round 7
// baseline (speedup 1.0000x reference)
#include <cuda_runtime.h>
#include <cuda_bf16.h>
#include <math.h>

#define HIDDEN 2048
#define NEXP   8
#define TOK_PER_WARP 4
#define WARPS_PER_BLOCK 8
#define TOK_PER_BLOCK (TOK_PER_WARP * WARPS_PER_BLOCK)   // 32
#define WSH_BYTES (NEXP * HIDDEN * 4)                    // 64 KB

// ---------------------------------------------------------------------------
// Packed fp32x2 FMA (sm_100+). ptxas never auto-fuses 2x fmaf into FFMA2;
// only PTX fma.rn.f32x2 reaches the double-rate fp32 path.
// ---------------------------------------------------------------------------
__device__ __forceinline__ void ffma2(unsigned long long& acc,
                                      unsigned long long a,
                                      unsigned long long b) {
    asm("fma.rn.f32x2 %0, %1, %2, %0;" : "+l"(acc) : "l"(a), "l"(b));
}

__device__ __forceinline__ float2 unpack_f32x2(unsigned long long v) {
    float2 r;
    asm("mov.b64 {%0, %1}, %2;" : "=f"(r.x), "=f"(r.y) : "l"(v));
    return r;
}

// Reference-matching sigmoid: 1/(1+exp(-x)) in fp32 with FTZ semantics.
// Tie-sets (which top_k's stable index-order tie-break acts on):
//   x >  16.636 : exactly 1.0f
//   x < -87.336 : exactly 0.0f (subnormal result flushed / exp overflow)
// Verified in R5/R6: index output matches exactly under this model.
__device__ __forceinline__ float ref_sigmoid(float x) {
    float s = 1.0f / (1.0f + expf(-x));
    if (s < 1.17549435e-38f) s = 0.0f;   // flush subnormal results (FTZ)
    return s;
}

// ---------------------------------------------------------------------------
// Persistent router kernel. Block caches the full 64 KB weight matrix in
// shared memory once (kills the L1-eviction latency chain that capped R6 at
// 61us), then loops over token tiles. Warp computes 8 expert scores for 4
// tokens; cross-lane reduce is a register butterfly (no smem scratch).
// ---------------------------------------------------------------------------
__global__ __launch_bounds__(256, 2)
void moe_router_kernel(const float* __restrict__ x,      // [N, HIDDEN]
                       const float* __restrict__ w,      // [NEXP, HIDDEN]
                       const float* __restrict__ bias,   // [NEXP]
                       float* __restrict__ out_w,        // [N, NEXP]
                       float* __restrict__ out_i,        // [N, NEXP] as float, or null
                       int N) {
    extern __shared__ float wsh[];   // [NEXP][HIDDEN] = 64 KB

    // ---- cache weights in smem (cooperative, float4) ----
    {
        const float4* src = reinterpret_cast<const float4*>(w);
        float4* dst = reinterpret_cast<float4*>(wsh);
#pragma unroll 4
        for (int i = threadIdx.x; i < NEXP * HIDDEN / 4; i += 256)
            dst[i] = src[i];
    }
    __syncthreads();

    const int warp = threadIdx.x >> 5;
    const int lane = threadIdx.x & 31;
    const int ntiles = N / TOK_PER_BLOCK;

    for (int tile = blockIdx.x; tile < ntiles; tile += gridDim.x) {
        const int tok0 = tile * TOK_PER_BLOCK + warp * TOK_PER_WARP;

        const unsigned long long* xp0 = reinterpret_cast<const unsigned long long*>(
            x + (size_t)tok0 * HIDDEN);
        const unsigned long long* xp1 = xp0 + (HIDDEN / 2);
        const unsigned long long* xp2 = xp0 + 2 * (HIDDEN / 2);
        const unsigned long long* xp3 = xp0 + 3 * (HIDDEN / 2);

        unsigned long long acc[TOK_PER_WARP][NEXP];
#pragma unroll
        for (int t = 0; t < TOK_PER_WARP; t++)
#pragma unroll
            for (int e = 0; e < NEXP; e++) acc[t][e] = 0ull;

        // 16 iterations x 32 lanes x 4 floats = 2048 = HIDDEN.
        // x: LDG.128 (DRAM stream, front-batched by unroll for MLP)
        // w: LDS.128 from smem (29cyc, never evicted)
#pragma unroll 4
        for (int i = 0; i < 16; i++) {
            const int p = (i * 32 + lane) * 2;  // pair units
            ulonglong2 xa = *reinterpret_cast<const ulonglong2*>(xp0 + p);
            ulonglong2 xb = *reinterpret_cast<const ulonglong2*>(xp1 + p);
            ulonglong2 xc = *reinterpret_cast<const ulonglong2*>(xp2 + p);
            ulonglong2 xd = *reinterpret_cast<const ulonglong2*>(xp3 + p);
#pragma unroll
            for (int e = 0; e < NEXP; e++) {
                ulonglong2 we = reinterpret_cast<const ulonglong2*>(
                    wsh + (size_t)e * HIDDEN)[i * 32 + lane];
                ffma2(acc[0][e], xa.x, we.x);
                ffma2(acc[0][e], xa.y, we.y);
                ffma2(acc[1][e], xb.x, we.x);
                ffma2(acc[1][e], xb.y, we.y);
                ffma2(acc[2][e], xc.x, we.x);
                ffma2(acc[2][e], xc.y, we.y);
                ffma2(acc[3][e], xd.x, we.x);
                ffma2(acc[3][e], xd.y, we.y);
            }
        }

        // ---- register butterfly: sum 32 per-lane partials across lanes.
        // After all stages, lane L holds the full sum for index L (= t*8+e).
        float vals[32];
#pragma unroll
        for (int t = 0; t < TOK_PER_WARP; t++)
#pragma unroll
            for (int e = 0; e < NEXP; e++) {
                float2 v = unpack_f32x2(acc[t][e]);
                vals[t * NEXP + e] = v.x + v.y;
            }
#pragma unroll
        for (int ofs = 16; ofs >= 1; ofs >>= 1) {
#pragma unroll
            for (int i = 0; i < 16; i++) {
                if (i < ofs) {
                    const bool hi = (lane & ofs) != 0;
                    float keep = hi ? vals[i + ofs] : vals[i];
                    float send = hi ? vals[i] : vals[i + ofs];
                    float recv = __shfl_xor_sync(0xFFFFFFFFu, send, ofs);
                    vals[i] = keep + recv;
                }
            }
        }
        const float logit = vals[0];

        // ---- epilogue: one (token, expert) per lane ----
        const int t = lane >> 3;
        const int e = lane & 7;

        float score = ref_sigmoid(logit);
        float sel   = score + bias[e];

        // sum of the 8 scores within each aligned 8-lane token group
        float tot = score;
        tot += __shfl_xor_sync(0xFFFFFFFFu, tot, 4);
        tot += __shfl_xor_sync(0xFFFFFFFFu, tot, 2);
        tot += __shfl_xor_sync(0xFFFFFFFFu, tot, 1);

        // stable descending rank: count (greater) or (equal with lower index)
        const int base = lane & 24;
        int rank = 0;
#pragma unroll
        for (int j = 0; j < NEXP; j++) {
            float sj = __shfl_sync(0xFFFFFFFFu, sel, base + j);
            rank += (sj > sel) || (sj == sel && j < e);
        }

        const float wv = (score / (tot + 1e-10f)) * 1.4f;
        const int tg = tok0 + t;
        out_w[(size_t)tg * NEXP + rank] = wv;
        if (out_i) out_i[(size_t)tg * NEXP + rank] = (float)e;
    }
}

// ---------------------------------------------------------------------------
// Harness entry
// ---------------------------------------------------------------------------
extern "C" void kernel_launch(void* const* d_in, const int* in_sizes, int n_in,
                              void* d_out, int out_size) {
    const float* x    = (const float*)d_in[0];   // hidden_states [4,8192,2048]
    const float* w    = (const float*)d_in[1];   // weight [8,2048]
    const float* bias = (const float*)d_in[2];   // e_score_correction_bias [8]

    const int N = in_sizes[0] / HIDDEN;          // 32768 tokens

    float* ow = (float*)d_out;                   // weights [N,8]
    float* oi = nullptr;                         // indices [N,8] as float
    if (out_size >= 2 * N * NEXP) oi = ow + (size_t)N * NEXP;

    cudaFuncSetAttribute(moe_router_kernel,
                         cudaFuncAttributeMaxDynamicSharedMemorySize, WSH_BYTES);

    int sms = 148;
    cudaDeviceGetAttribute(&sms, cudaDevAttrMultiProcessorCount, 0);
    int blocks = 2 * sms;                        // persistent: 2 blocks/SM
    int ntiles = N / TOK_PER_BLOCK;
    if (blocks > ntiles) blocks = ntiles;

    moe_router_kernel<<<blocks, 256, WSH_BYTES>>>(x, w, bias, ow, oi, N);
}

// round 8
// speedup vs baseline: 1.0775x; 1.0775x over previous
#include <cuda_runtime.h>
#include <cuda_bf16.h>
#include <math.h>

#define HIDDEN 2048
#define NEXP   8
#define TOK_PER_WARP 4
#define WARPS_PER_BLOCK 8
#define TOK_PER_BLOCK (TOK_PER_WARP * WARPS_PER_BLOCK)   // 32

// ---------------------------------------------------------------------------
// Packed fp32x2 FMA (sm_100+). ptxas never auto-fuses 2x fmaf into FFMA2;
// only PTX fma.rn.f32x2 reaches the double-rate fp32 path.
// ---------------------------------------------------------------------------
__device__ __forceinline__ void ffma2(unsigned long long& acc,
                                      unsigned long long a,
                                      unsigned long long b) {
    asm("fma.rn.f32x2 %0, %1, %2, %0;" : "+l"(acc) : "l"(a), "l"(b));
}

__device__ __forceinline__ float2 unpack_f32x2(unsigned long long v) {
    float2 r;
    asm("mov.b64 {%0, %1}, %2;" : "=f"(r.x), "=f"(r.y) : "l"(v));
    return r;
}

// Reference-matching sigmoid: 1/(1+exp(-x)) in fp32 with FTZ semantics.
// Tie-sets (which top_k's stable index-order tie-break acts on):
//   x >  16.636 : exactly 1.0f
//   x < -87.336 : exactly 0.0f (subnormal result flushed / exp overflow)
// Verified R5-R7: index output matches exactly under this model.
__device__ __forceinline__ float ref_sigmoid(float x) {
    float s = 1.0f / (1.0f + expf(-x));
    if (s < 1.17549435e-38f) s = 0.0f;   // flush subnormal results (FTZ)
    return s;
}

// ---------------------------------------------------------------------------
// Router kernel: warp computes 8 expert sigmoid scores for 4 tokens.
// x loads: __ldcs (evict-first streaming; keeps the 64KB weight matrix
// L1-resident) with a manual 1-deep register prefetch pipeline so every
// warp keeps 4 LDG.128 in flight during the FFMA block (R6/R7 were
// DRAM-latency exposed: regs capped ptxas's own load batching).
// ---------------------------------------------------------------------------
__global__ __launch_bounds__(256, 2)
void moe_router_kernel(const float* __restrict__ x,      // [N, HIDDEN]
                       const float* __restrict__ w,      // [NEXP, HIDDEN]
                       const float* __restrict__ bias,   // [NEXP]
                       float* __restrict__ out_w,        // [N, NEXP]
                       float* __restrict__ out_i,        // [N, NEXP] as float, or null
                       int N) {
    // transpose-reduce scratch: [warp][lane][32 partials], pad 33 -> conflict-free
    __shared__ float red[WARPS_PER_BLOCK][32][TOK_PER_WARP * NEXP + 1];

    const int warp = threadIdx.x >> 5;
    const int lane = threadIdx.x & 31;
    const int tok0 = (blockIdx.x * WARPS_PER_BLOCK + warp) * TOK_PER_WARP;
    if (tok0 >= N) return;

    const unsigned long long* xp0 = reinterpret_cast<const unsigned long long*>(
        x + (size_t)tok0 * HIDDEN);
    const unsigned long long* xp1 = xp0 + (HIDDEN / 2);
    const unsigned long long* xp2 = xp0 + 2 * (HIDDEN / 2);
    const unsigned long long* xp3 = xp0 + 3 * (HIDDEN / 2);
    const unsigned long long* wp  = reinterpret_cast<const unsigned long long*>(w);

    unsigned long long acc[TOK_PER_WARP][NEXP];
#pragma unroll
    for (int t = 0; t < TOK_PER_WARP; t++)
#pragma unroll
        for (int e = 0; e < NEXP; e++) acc[t][e] = 0ull;

    // ---- software-pipelined main loop ----
    // prefetch iteration 0 (4 x LDG.128, streaming)
    int p = lane * 2;  // pair units
    ulonglong2 xa = __ldcs(reinterpret_cast<const ulonglong2*>(xp0 + p));
    ulonglong2 xb = __ldcs(reinterpret_cast<const ulonglong2*>(xp1 + p));
    ulonglong2 xc = __ldcs(reinterpret_cast<const ulonglong2*>(xp2 + p));
    ulonglong2 xd = __ldcs(reinterpret_cast<const ulonglong2*>(xp3 + p));

#pragma unroll
    for (int i = 0; i < 16; i++) {
        const int pc = p;                 // offsets for this iteration's data
        ulonglong2 ca = xa, cb = xb, cc = xc, cd = xd;
        if (i < 15) {                     // issue next iteration's loads NOW
            p = ((i + 1) * 32 + lane) * 2;
            xa = __ldcs(reinterpret_cast<const ulonglong2*>(xp0 + p));
            xb = __ldcs(reinterpret_cast<const ulonglong2*>(xp1 + p));
            xc = __ldcs(reinterpret_cast<const ulonglong2*>(xp2 + p));
            xd = __ldcs(reinterpret_cast<const ulonglong2*>(xp3 + p));
        }
#pragma unroll
        for (int e = 0; e < NEXP; e++) {
            ulonglong2 we = *reinterpret_cast<const ulonglong2*>(
                wp + (size_t)e * (HIDDEN / 2) + pc);   // L1-resident (x is .cs)
            ffma2(acc[0][e], ca.x, we.x);
            ffma2(acc[0][e], ca.y, we.y);
            ffma2(acc[1][e], cb.x, we.x);
            ffma2(acc[1][e], cb.y, we.y);
            ffma2(acc[2][e], cc.x, we.x);
            ffma2(acc[2][e], cc.y, we.y);
            ffma2(acc[3][e], cd.x, we.x);
            ffma2(acc[3][e], cd.y, we.y);
        }
    }

    // per-lane partial sums -> smem transpose
#pragma unroll
    for (int t = 0; t < TOK_PER_WARP; t++)
#pragma unroll
        for (int e = 0; e < NEXP; e++) {
            float2 v = unpack_f32x2(acc[t][e]);
            red[warp][lane][t * NEXP + e] = v.x + v.y;
        }
    __syncwarp();

    // all 32 lanes: one (token, expert) each. Sum 32 lane-partials.
    {
        const int t = lane >> 3;
        const int e = lane & 7;

        float logit = 0.0f;
#pragma unroll
        for (int j = 0; j < 32; j++) logit += red[warp][j][lane];

        float score = ref_sigmoid(logit);
        float sel   = score + bias[e];

        // sum of the 8 scores within each aligned 8-lane token group
        float tot = score;
        tot += __shfl_xor_sync(0xFFFFFFFFu, tot, 4);
        tot += __shfl_xor_sync(0xFFFFFFFFu, tot, 2);
        tot += __shfl_xor_sync(0xFFFFFFFFu, tot, 1);

        // stable descending rank: count (greater) or (equal with lower index)
        const int base = lane & 24;
        int rank = 0;
#pragma unroll
        for (int j = 0; j < NEXP; j++) {
            float sj = __shfl_sync(0xFFFFFFFFu, sel, base + j);
            rank += (sj > sel) || (sj == sel && j < e);
        }

        const float wv = (score / (tot + 1e-10f)) * 1.4f;
        const int tg = tok0 + t;
        out_w[(size_t)tg * NEXP + rank] = wv;
        if (out_i) out_i[(size_t)tg * NEXP + rank] = (float)e;
    }
}

// ---------------------------------------------------------------------------
// Harness entry
// ---------------------------------------------------------------------------
extern "C" void kernel_launch(void* const* d_in, const int* in_sizes, int n_in,
                              void* d_out, int out_size) {
    const float* x    = (const float*)d_in[0];   // hidden_states [4,8192,2048]
    const float* w    = (const float*)d_in[1];   // weight [8,2048]
    const float* bias = (const float*)d_in[2];   // e_score_correction_bias [8]

    const int N = in_sizes[0] / HIDDEN;          // 32768 tokens

    float* ow = (float*)d_out;                   // weights [N,8]
    float* oi = nullptr;                         // indices [N,8] as float
    if (out_size >= 2 * N * NEXP) oi = ow + (size_t)N * NEXP;

    dim3 grid((N + TOK_PER_BLOCK - 1) / TOK_PER_BLOCK);
    moe_router_kernel<<<grid, 256>>>(x, w, bias, ow, oi, N);
}